// round 11
// baseline (speedup 1.0000x reference)
#include <cuda_runtime.h>
#include <cuda_fp16.h>
#include <math.h>

#define NF   40
#define DD   64
#define AA   32
#define NROW 48          // padded M rows (3 m16 tiles)
#define NCOL 40          // N (5 n8 tiles)
#define NTH  192         // 6 warps
#define NW   6
#define XS   68          // sx row stride (floats), 17 float4
#define NA   33          // 32 attn cols + p

// permuted k location: float4 at (tig*16 + kb*4) of a row holds k-values
// {16kb+2tig, 16kb+2tig+1, 16kb+2tig+8, 16kb+2tig+9}
__device__ __forceinline__ int kloc(int k) {
    return (((k >> 1) & 3) << 4) | ((k >> 4) << 2) | (((k >> 3) & 1) << 1) | (k & 1);
}

__device__ __forceinline__ unsigned h2(float lo, float hi) {
    __half2 h = __floats2half2_rn(lo, hi);
    return *reinterpret_cast<unsigned*>(&h);
}
__device__ __forceinline__ unsigned hmul2u(unsigned a, unsigned b) {
    __half2 r = __hmul2(*reinterpret_cast<__half2*>(&a), *reinterpret_cast<__half2*>(&b));
    return *reinterpret_cast<unsigned*>(&r);
}

__device__ __forceinline__ void mma_f16(float c[4],
                                        unsigned a0, unsigned a1, unsigned a2, unsigned a3,
                                        unsigned b0, unsigned b1) {
    asm("mma.sync.aligned.m16n8k16.row.col.f32.f16.f16.f32 "
        "{%0,%1,%2,%3}, {%4,%5,%6,%7}, {%8,%9}, {%0,%1,%2,%3};"
        : "+f"(c[0]), "+f"(c[1]), "+f"(c[2]), "+f"(c[3])
        : "r"(a0), "r"(a1), "r"(a2), "r"(a3), "r"(b0), "r"(b1));
}

__global__ __launch_bounds__(NTH, 3)
void afm_kernel(const float* __restrict__ x,
                const float* __restrict__ W1,
                const float* __restrict__ b1,
                const float* __restrict__ w2,
                const float* __restrict__ pvec,
                float* __restrict__ out)
{
    __shared__ __align__(16) float sx[NROW * XS];   // k-permuted X, zero-padded rows
    __shared__ uint2 sWh[NA * 16];   // scale half2 pairs: [(a*4+kb)*4 + tig]
    __shared__ float sb1[AA], sw2[AA];
    __shared__ float sL0[NROW * NCOL];   // partial logits, a-group 0
    __shared__ float sL1[NROW * NCOL];   // partial logits, a-group 1
    __shared__ float sS [NROW * NCOL];   // s matrix (prod . p)
    __shared__ float red[32];

    const int b    = blockIdx.x;
    const int tid  = threadIdx.x;
    const int lane = tid & 31;
    const int wrp  = tid >> 5;
    const int gid  = lane >> 2;   // 0..7
    const int tig  = lane & 3;    // 0..3
    const int wg   = wrp % 3;     // tile-set id
    const int ag   = wrp / 3;     // a-group

    // tile lists: wg0: (0,0)(0,1)(0,2)  wg1: (0,3)(0,4)(1,2)  wg2: (1,3)(1,4)(2,4)
    const int mA0 = (wg == 2) ? 1 : 0;
    const int mA1 = wg;
    const int nb0 = (wg == 0) ? 0 : 3;
    const int nb1 = (wg == 0) ? 1 : 4;
    const int nb2 = (wg == 0) ? 2 : ((wg == 1) ? 2 : 4);

    // ---- stage permuted X (rows >= 40 zeroed) ----
    const float* xb = x + (size_t)b * (NF * DD);
    for (int t = tid; t < NROW * DD; t += NTH) {
        int f = t >> 6, k = t & 63;
        sx[f * XS + kloc(k)] = (f < NF) ? xb[f * DD + k] : 0.0f;
    }
    // ---- stage scale half2 pairs: a<32 -> W1 col, a==32 -> p ----
    for (int t = tid; t < NA * 16; t += NTH) {
        int a = t >> 4, r = t & 15, kb = r >> 2, tg = r & 3;
        int k0 = kb * 16 + 2 * tg;
        float w0, w1, w8, w9;
        if (a < AA) {
            w0 = W1[k0 * AA + a];       w1 = W1[(k0 + 1) * AA + a];
            w8 = W1[(k0 + 8) * AA + a]; w9 = W1[(k0 + 9) * AA + a];
        } else {
            w0 = pvec[k0];     w1 = pvec[k0 + 1];
            w8 = pvec[k0 + 8]; w9 = pvec[k0 + 9];
        }
        sWh[t] = make_uint2(h2(w0, w1), h2(w8, w9));
    }
    if (tid < AA) { sb1[tid] = b1[tid]; sw2[tid] = w2[tid]; }
    __syncthreads();

    // ---- load this warp's A / B fragments of X once (register-resident) ----
    const float4* sx4 = (const float4*)sx;     // row stride 17 float4
    unsigned Ax[2][4][4];
    #pragma unroll
    for (int s = 0; s < 2; s++) {
        const int rr = (s ? mA1 : mA0) * 16 + gid;
        #pragma unroll
        for (int kb = 0; kb < 4; kb++) {
            float4 v0 = sx4[rr * 17 + tig * 4 + kb];
            float4 v1 = sx4[(rr + 8) * 17 + tig * 4 + kb];
            Ax[s][kb][0] = h2(v0.x, v0.y);  Ax[s][kb][2] = h2(v0.z, v0.w);
            Ax[s][kb][1] = h2(v1.x, v1.y);  Ax[s][kb][3] = h2(v1.z, v1.w);
        }
    }
    unsigned Bx[3][4][2];
    #pragma unroll
    for (int t = 0; t < 3; t++) {
        const int rb = ((t == 0) ? nb0 : (t == 1) ? nb1 : nb2) * 8 + gid;
        #pragma unroll
        for (int kb = 0; kb < 4; kb++) {
            float4 v = sx4[rb * 17 + tig * 4 + kb];
            Bx[t][kb][0] = h2(v.x, v.y);
            Bx[t][kb][1] = h2(v.z, v.w);
        }
    }

    // ---- a-loop unrolled x2: 6 independent G chains ----
    float logit[3][4];
    #pragma unroll
    for (int t = 0; t < 3; t++)
        { logit[t][0] = logit[t][1] = logit[t][2] = logit[t][3] = 0.0f; }

    #pragma unroll 1
    for (int ai = 0; ai < 16; ai += 2) {
        const int a0 = ag * 16 + ai;
        const int a1 = a0 + 1;

        float G0[3][4], G1[3][4];
        #pragma unroll
        for (int t = 0; t < 3; t++) {
            G0[t][0] = G0[t][1] = G0[t][2] = G0[t][3] = 0.0f;
            G1[t][0] = G1[t][1] = G1[t][2] = G1[t][3] = 0.0f;
        }
        #pragma unroll
        for (int kb = 0; kb < 4; kb++) {
            uint2 c0 = sWh[(a0 * 4 + kb) * 4 + tig];
            uint2 c1 = sWh[(a1 * 4 + kb) * 4 + tig];
            #pragma unroll
            for (int t = 0; t < 3; t++) {
                const int s = (t == 2) ? 1 : 0;
                unsigned z00 = hmul2u(Bx[t][kb][0], c0.x);
                unsigned z01 = hmul2u(Bx[t][kb][1], c0.y);
                mma_f16(G0[t], Ax[s][kb][0], Ax[s][kb][1], Ax[s][kb][2], Ax[s][kb][3], z00, z01);
                unsigned z10 = hmul2u(Bx[t][kb][0], c1.x);
                unsigned z11 = hmul2u(Bx[t][kb][1], c1.y);
                mma_f16(G1[t], Ax[s][kb][0], Ax[s][kb][1], Ax[s][kb][2], Ax[s][kb][3], z10, z11);
            }
        }
        const float bb0 = sb1[a0], ww0 = sw2[a0];
        const float bb1 = sb1[a1], ww1 = sw2[a1];
        #pragma unroll
        for (int t = 0; t < 3; t++)
            #pragma unroll
            for (int q = 0; q < 4; q++) {
                logit[t][q] = fmaf(fmaxf(G0[t][q] + bb0, 0.0f), ww0, logit[t][q]);
                logit[t][q] = fmaf(fmaxf(G1[t][q] + bb1, 0.0f), ww1, logit[t][q]);
            }
    }

    // ---- p pass (a-group 0 only): s = x_i^T diag(p) x_j -> sS ----
    if (ag == 0) {
        float G[3][4];
        #pragma unroll
        for (int t = 0; t < 3; t++)
            { G[t][0] = G[t][1] = G[t][2] = G[t][3] = 0.0f; }
        #pragma unroll
        for (int kb = 0; kb < 4; kb++) {
            uint2 sc = sWh[(AA * 4 + kb) * 4 + tig];
            #pragma unroll
            for (int t = 0; t < 3; t++) {
                unsigned z0 = hmul2u(Bx[t][kb][0], sc.x);
                unsigned z1 = hmul2u(Bx[t][kb][1], sc.y);
                const int s = (t == 2) ? 1 : 0;
                mma_f16(G[t], Ax[s][kb][0], Ax[s][kb][1], Ax[s][kb][2], Ax[s][kb][3], z0, z1);
            }
        }
        #pragma unroll
        for (int t = 0; t < 3; t++) {
            const int mt = (t == 2) ? mA1 : mA0;
            const int nt = (t == 0) ? nb0 : (t == 1) ? nb1 : nb2;
            const int m0 = mt * 16 + gid, j0 = nt * 8 + 2 * tig;
            sS[m0 * NCOL + j0]           = G[t][0];
            sS[m0 * NCOL + j0 + 1]       = G[t][1];
            sS[(m0 + 8) * NCOL + j0]     = G[t][2];
            sS[(m0 + 8) * NCOL + j0 + 1] = G[t][3];
        }
    }

    // ---- write partial logits ----
    {
        float* dst = ag ? sL1 : sL0;
        #pragma unroll
        for (int t = 0; t < 3; t++) {
            const int mt = (t == 2) ? mA1 : mA0;
            const int nt = (t == 0) ? nb0 : (t == 1) ? nb1 : nb2;
            const int m0 = mt * 16 + gid, j0 = nt * 8 + 2 * tig;
            dst[m0 * NCOL + j0]           = logit[t][0];
            dst[m0 * NCOL + j0 + 1]       = logit[t][1];
            dst[(m0 + 8) * NCOL + j0]     = logit[t][2];
            dst[(m0 + 8) * NCOL + j0 + 1] = logit[t][3];
        }
    }
    __syncthreads();

    // ---- masked softmax over strict upper triangle (j > i) + weighted sum ----
    float lmax = -INFINITY;
    for (int t = tid; t < NF * NCOL; t += NTH) {
        int i = t / NCOL, j = t - i * NCOL;
        if (j > i) lmax = fmaxf(lmax, sL0[t] + sL1[t]);
    }
    #pragma unroll
    for (int o = 16; o > 0; o >>= 1)
        lmax = fmaxf(lmax, __shfl_xor_sync(0xFFFFFFFFu, lmax, o));
    if (lane == 0) red[wrp] = lmax;
    __syncthreads();
    if (tid == 0) {
        float m = red[0];
        #pragma unroll
        for (int w = 1; w < NW; w++) m = fmaxf(m, red[w]);
        red[16] = m;
    }
    __syncthreads();
    const float mx = red[16];

    float num = 0.0f, den = 0.0f;
    for (int t = tid; t < NF * NCOL; t += NTH) {
        int i = t / NCOL, j = t - i * NCOL;
        if (j > i) {
            float e = __expf(sL0[t] + sL1[t] - mx);
            num = fmaf(e, sS[t], num);
            den += e;
        }
    }
    #pragma unroll
    for (int o = 16; o > 0; o >>= 1) {
        num += __shfl_xor_sync(0xFFFFFFFFu, num, o);
        den += __shfl_xor_sync(0xFFFFFFFFu, den, o);
    }
    __syncthreads();
    if (lane == 0) { red[wrp] = num; red[8 + wrp] = den; }
    __syncthreads();
    if (tid == 0) {
        float n = 0.0f, d = 0.0f;
        #pragma unroll
        for (int w = 0; w < NW; w++) { n += red[w]; d += red[8 + w]; }
        out[b] = n / d;
    }
}

extern "C" void kernel_launch(void* const* d_in, const int* in_sizes, int n_in,
                              void* d_out, int out_size)
{
    const float* x    = (const float*)d_in[0];
    const float* W1   = (const float*)d_in[1];
    const float* b1   = (const float*)d_in[2];
    const float* w2   = (const float*)d_in[3];
    const float* pvec = (const float*)d_in[4];
    float* out = (float*)d_out;

    int B = in_sizes[0] / (NF * DD);
    afm_kernel<<<B, NTH>>>(x, W1, b1, w2, pvec, out);
}

// round 12
// speedup vs baseline: 1.3627x; 1.3627x over previous
#include <cuda_runtime.h>
#include <cuda_fp16.h>
#include <math.h>

#define NF   40
#define DD   64
#define AA   32
#define NROW 48          // padded M rows (3 m16 tiles)
#define NCOL 40          // N (5 n8 tiles)
#define NTH  288         // 9 warps: one tile per warp
#define NW   9
#define XS   68          // sx row stride (floats), 17 float4
#define NA   33          // 32 attn cols + p

// permuted k location: float4 at (tig*16 + kb*4) of a row holds k-values
// {16kb+2tig, 16kb+2tig+1, 16kb+2tig+8, 16kb+2tig+9}
__device__ __forceinline__ int kloc(int k) {
    return (((k >> 1) & 3) << 4) | ((k >> 4) << 2) | (((k >> 3) & 1) << 1) | (k & 1);
}

__device__ __forceinline__ unsigned h2(float lo, float hi) {
    __half2 h = __floats2half2_rn(lo, hi);
    return *reinterpret_cast<unsigned*>(&h);
}
__device__ __forceinline__ unsigned hmul2u(unsigned a, unsigned b) {
    __half2 r = __hmul2(*reinterpret_cast<__half2*>(&a), *reinterpret_cast<__half2*>(&b));
    return *reinterpret_cast<unsigned*>(&r);
}

__device__ __forceinline__ void mma_f16(float c[4],
                                        unsigned a0, unsigned a1, unsigned a2, unsigned a3,
                                        unsigned b0, unsigned b1) {
    asm("mma.sync.aligned.m16n8k16.row.col.f32.f16.f16.f32 "
        "{%0,%1,%2,%3}, {%4,%5,%6,%7}, {%8,%9}, {%0,%1,%2,%3};"
        : "+f"(c[0]), "+f"(c[1]), "+f"(c[2]), "+f"(c[3])
        : "r"(a0), "r"(a1), "r"(a2), "r"(a3), "r"(b0), "r"(b1));
}

__global__ __launch_bounds__(NTH, 3)
void afm_kernel(const float* __restrict__ x,
                const float* __restrict__ W1,
                const float* __restrict__ b1,
                const float* __restrict__ w2,
                const float* __restrict__ pvec,
                float* __restrict__ out)
{
    __shared__ __align__(16) float sx[NROW * XS];   // k-permuted X, zero-padded rows
    __shared__ uint2 sWh[NA * 16];   // scale half2 pairs: [(a*4+kb)*4 + tig]
    __shared__ float sb1[AA], sw2[AA];
    __shared__ float sL[NROW * NCOL];    // logits (full, per-tile complete)
    __shared__ float sS[NROW * NCOL];    // s matrix (prod . p)
    __shared__ float red[40];

    const int b    = blockIdx.x;
    const int tid  = threadIdx.x;
    const int lane = tid & 31;
    const int wrp  = tid >> 5;
    const int gid  = lane >> 2;   // 0..7
    const int tig  = lane & 3;    // 0..3

    // warp -> tile: {(0,0),(0,1),(0,2),(0,3),(0,4),(1,2),(1,3),(1,4),(2,4)}
    const int mt = (wrp < 5) ? 0 : ((wrp < 8) ? 1 : 2);
    const int nt = (wrp < 5) ? wrp : ((wrp < 8) ? (wrp - 3) : 4);

    // ---- stage permuted X (rows >= 40 zeroed) ----
    const float* xb = x + (size_t)b * (NF * DD);
    for (int t = tid; t < NROW * DD; t += NTH) {
        int f = t >> 6, k = t & 63;
        sx[f * XS + kloc(k)] = (f < NF) ? xb[f * DD + k] : 0.0f;
    }
    // ---- stage scale half2 pairs: a<32 -> W1 col, a==32 -> p ----
    for (int t = tid; t < NA * 16; t += NTH) {
        int a = t >> 4, r = t & 15, kb = r >> 2, tg = r & 3;
        int k0 = kb * 16 + 2 * tg;
        float w0, w1, w8, w9;
        if (a < AA) {
            w0 = W1[k0 * AA + a];       w1 = W1[(k0 + 1) * AA + a];
            w8 = W1[(k0 + 8) * AA + a]; w9 = W1[(k0 + 9) * AA + a];
        } else {
            w0 = pvec[k0];     w1 = pvec[k0 + 1];
            w8 = pvec[k0 + 8]; w9 = pvec[k0 + 9];
        }
        sWh[t] = make_uint2(h2(w0, w1), h2(w8, w9));
    }
    if (tid < AA) { sb1[tid] = b1[tid]; sw2[tid] = w2[tid]; }
    __syncthreads();

    // ---- load this warp's A / B fragments of X once (register-resident) ----
    const float4* sx4 = (const float4*)sx;     // row stride 17 float4
    unsigned Ax[4][4];
    {
        const int rr = mt * 16 + gid;
        #pragma unroll
        for (int kb = 0; kb < 4; kb++) {
            float4 v0 = sx4[rr * 17 + tig * 4 + kb];
            float4 v1 = sx4[(rr + 8) * 17 + tig * 4 + kb];
            Ax[kb][0] = h2(v0.x, v0.y);  Ax[kb][2] = h2(v0.z, v0.w);
            Ax[kb][1] = h2(v1.x, v1.y);  Ax[kb][3] = h2(v1.z, v1.w);
        }
    }
    unsigned Bx[4][2];
    {
        const int rb = nt * 8 + gid;
        #pragma unroll
        for (int kb = 0; kb < 4; kb++) {
            float4 v = sx4[rb * 17 + tig * 4 + kb];
            Bx[kb][0] = h2(v.x, v.y);
            Bx[kb][1] = h2(v.z, v.w);
        }
    }

    // ---- a-loop (all 32 a's), unrolled x2: 2 independent G chains ----
    float logit[4] = {0.0f, 0.0f, 0.0f, 0.0f};

    #pragma unroll 1
    for (int a0 = 0; a0 < AA; a0 += 2) {
        const int a1 = a0 + 1;
        float G0[4] = {0.0f, 0.0f, 0.0f, 0.0f};
        float G1[4] = {0.0f, 0.0f, 0.0f, 0.0f};
        #pragma unroll
        for (int kb = 0; kb < 4; kb++) {
            uint2 c0 = sWh[(a0 * 4 + kb) * 4 + tig];
            uint2 c1 = sWh[(a1 * 4 + kb) * 4 + tig];
            unsigned z00 = hmul2u(Bx[kb][0], c0.x);
            unsigned z01 = hmul2u(Bx[kb][1], c0.y);
            mma_f16(G0, Ax[kb][0], Ax[kb][1], Ax[kb][2], Ax[kb][3], z00, z01);
            unsigned z10 = hmul2u(Bx[kb][0], c1.x);
            unsigned z11 = hmul2u(Bx[kb][1], c1.y);
            mma_f16(G1, Ax[kb][0], Ax[kb][1], Ax[kb][2], Ax[kb][3], z10, z11);
        }
        const float bb0 = sb1[a0], ww0 = sw2[a0];
        const float bb1 = sb1[a1], ww1 = sw2[a1];
        #pragma unroll
        for (int q = 0; q < 4; q++) {
            logit[q] = fmaf(fmaxf(G0[q] + bb0, 0.0f), ww0, logit[q]);
            logit[q] = fmaf(fmaxf(G1[q] + bb1, 0.0f), ww1, logit[q]);
        }
    }

    // ---- p pass: s = x_i^T diag(p) x_j for this tile -> sS ----
    {
        float G[4] = {0.0f, 0.0f, 0.0f, 0.0f};
        #pragma unroll
        for (int kb = 0; kb < 4; kb++) {
            uint2 sc = sWh[(AA * 4 + kb) * 4 + tig];
            unsigned z0 = hmul2u(Bx[kb][0], sc.x);
            unsigned z1 = hmul2u(Bx[kb][1], sc.y);
            mma_f16(G, Ax[kb][0], Ax[kb][1], Ax[kb][2], Ax[kb][3], z0, z1);
        }
        const int m0 = mt * 16 + gid, j0 = nt * 8 + 2 * tig;
        sS[m0 * NCOL + j0]           = G[0];
        sS[m0 * NCOL + j0 + 1]       = G[1];
        sS[(m0 + 8) * NCOL + j0]     = G[2];
        sS[(m0 + 8) * NCOL + j0 + 1] = G[3];
        sL[m0 * NCOL + j0]           = logit[0];
        sL[m0 * NCOL + j0 + 1]       = logit[1];
        sL[(m0 + 8) * NCOL + j0]     = logit[2];
        sL[(m0 + 8) * NCOL + j0 + 1] = logit[3];
    }
    __syncthreads();

    // ---- masked softmax over strict upper triangle (j > i) + weighted sum ----
    float lmax = -INFINITY;
    for (int t = tid; t < NF * NCOL; t += NTH) {
        int i = t / NCOL, j = t - i * NCOL;
        if (j > i) lmax = fmaxf(lmax, sL[t]);
    }
    #pragma unroll
    for (int o = 16; o > 0; o >>= 1)
        lmax = fmaxf(lmax, __shfl_xor_sync(0xFFFFFFFFu, lmax, o));
    if (lane == 0) red[wrp] = lmax;
    __syncthreads();
    if (tid == 0) {
        float m = red[0];
        #pragma unroll
        for (int w = 1; w < NW; w++) m = fmaxf(m, red[w]);
        red[32] = m;
    }
    __syncthreads();
    const float mx = red[32];

    float num = 0.0f, den = 0.0f;
    for (int t = tid; t < NF * NCOL; t += NTH) {
        int i = t / NCOL, j = t - i * NCOL;
        if (j > i) {
            float e = __expf(sL[t] - mx);
            num = fmaf(e, sS[t], num);
            den += e;
        }
    }
    #pragma unroll
    for (int o = 16; o > 0; o >>= 1) {
        num += __shfl_xor_sync(0xFFFFFFFFu, num, o);
        den += __shfl_xor_sync(0xFFFFFFFFu, den, o);
    }
    __syncthreads();
    if (lane == 0) { red[wrp] = num; red[16 + wrp] = den; }
    __syncthreads();
    if (tid == 0) {
        float n = 0.0f, d = 0.0f;
        #pragma unroll
        for (int w = 0; w < NW; w++) { n += red[w]; d += red[16 + w]; }
        out[b] = n / d;
    }
}

extern "C" void kernel_launch(void* const* d_in, const int* in_sizes, int n_in,
                              void* d_out, int out_size)
{
    const float* x    = (const float*)d_in[0];
    const float* W1   = (const float*)d_in[1];
    const float* b1   = (const float*)d_in[2];
    const float* w2   = (const float*)d_in[3];
    const float* pvec = (const float*)d_in[4];
    float* out = (float*)d_out;

    int B = in_sizes[0] / (NF * DD);
    afm_kernel<<<B, NTH>>>(x, W1, b1, w2, pvec, out);
}

// round 13
// speedup vs baseline: 1.4434x; 1.0592x over previous
#include <cuda_runtime.h>
#include <cuda_fp16.h>
#include <math.h>

#define NF   40
#define DD   64
#define AA   32
#define NROW 48          // padded M rows (3 m16 tiles)
#define NCOL 40          // N (5 n8 tiles)
#define NTH  288         // 9 warps: one tile per warp
#define NW   9
#define XS   68          // sx row stride (floats), 17 float4
#define NA   33          // 32 attn cols + p

// permuted k location: float4 at (tig*16 + kb*4) of a row holds k-values
// {16kb+2tig, 16kb+2tig+1, 16kb+2tig+8, 16kb+2tig+9}
__device__ __forceinline__ int kloc(int k) {
    return (((k >> 1) & 3) << 4) | ((k >> 4) << 2) | (((k >> 3) & 1) << 1) | (k & 1);
}

__device__ __forceinline__ unsigned h2(float lo, float hi) {
    __half2 h = __floats2half2_rn(lo, hi);
    return *reinterpret_cast<unsigned*>(&h);
}
__device__ __forceinline__ unsigned hmul2u(unsigned a, unsigned b) {
    __half2 r = __hmul2(*reinterpret_cast<__half2*>(&a), *reinterpret_cast<__half2*>(&b));
    return *reinterpret_cast<unsigned*>(&r);
}

__device__ __forceinline__ void mma_f16(float c[4],
                                        unsigned a0, unsigned a1, unsigned a2, unsigned a3,
                                        unsigned b0, unsigned b1) {
    asm("mma.sync.aligned.m16n8k16.row.col.f32.f16.f16.f32 "
        "{%0,%1,%2,%3}, {%4,%5,%6,%7}, {%8,%9}, {%0,%1,%2,%3};"
        : "+f"(c[0]), "+f"(c[1]), "+f"(c[2]), "+f"(c[3])
        : "r"(a0), "r"(a1), "r"(a2), "r"(a3), "r"(b0), "r"(b1));
}

__global__ __launch_bounds__(NTH, 3)
void afm_kernel(const float* __restrict__ x,
                const float* __restrict__ W1,
                const float* __restrict__ b1,
                const float* __restrict__ w2,
                const float* __restrict__ pvec,
                float* __restrict__ out)
{
    __shared__ __align__(16) float sx[NROW * XS];   // k-permuted X, zero-padded rows
    // scale pack: per (a, tig) two uint4 covering kb=0..3:
    //   sWh4[(a*4 + tig)*2 + 0] = {c0.x, c0.y, c1.x, c1.y}   (kb 0,1)
    //   sWh4[(a*4 + tig)*2 + 1] = {c2.x, c2.y, c3.x, c3.y}   (kb 2,3)
    // where ckb = (h2(w[k0],w[k0+1]), h2(w[k0+8],w[k0+9])), k0 = kb*16 + 2*tig
    __shared__ __align__(16) uint4 sWh4[NA * 8];
    __shared__ float sb1[AA], sw2[AA];
    __shared__ float sL[NROW * NCOL];    // logits
    __shared__ float sS[NROW * NCOL];    // s matrix (prod . p)
    __shared__ float red[40];

    const int b    = blockIdx.x;
    const int tid  = threadIdx.x;
    const int lane = tid & 31;
    const int wrp  = tid >> 5;
    const int gid  = lane >> 2;   // 0..7
    const int tig  = lane & 3;    // 0..3

    // warp -> tile: {(0,0),(0,1),(0,2),(0,3),(0,4),(1,2),(1,3),(1,4),(2,4)}
    const int mt = (wrp < 5) ? 0 : ((wrp < 8) ? 1 : 2);
    const int nt = (wrp < 5) ? wrp : ((wrp < 8) ? (wrp - 3) : 4);

    // ---- stage permuted X (rows >= 40 zeroed) ----
    const float* xb = x + (size_t)b * (NF * DD);
    for (int t = tid; t < NROW * DD; t += NTH) {
        int f = t >> 6, k = t & 63;
        sx[f * XS + kloc(k)] = (f < NF) ? xb[f * DD + k] : 0.0f;
    }
    // ---- stage packed scales: a<32 -> W1 col, a==32 -> p ----
    for (int t = tid; t < NA * 8; t += NTH) {
        int a = t >> 3, r = t & 7, tg = r >> 1, hh = r & 1;
        uint4 u;
        #pragma unroll
        for (int kk = 0; kk < 2; kk++) {
            int kb = hh * 2 + kk;
            int k0 = kb * 16 + 2 * tg;
            float w0, w1, w8, w9;
            if (a < AA) {
                w0 = W1[k0 * AA + a];       w1 = W1[(k0 + 1) * AA + a];
                w8 = W1[(k0 + 8) * AA + a]; w9 = W1[(k0 + 9) * AA + a];
            } else {
                w0 = pvec[k0];     w1 = pvec[k0 + 1];
                w8 = pvec[k0 + 8]; w9 = pvec[k0 + 9];
            }
            if (kk == 0) { u.x = h2(w0, w1); u.y = h2(w8, w9); }
            else         { u.z = h2(w0, w1); u.w = h2(w8, w9); }
        }
        sWh4[t] = u;
    }
    if (tid < AA) { sb1[tid] = b1[tid]; sw2[tid] = w2[tid]; }
    __syncthreads();

    // ---- load this warp's A / B fragments of X once (register-resident) ----
    const float4* sx4 = (const float4*)sx;     // row stride 17 float4
    unsigned Ax[4][4];
    {
        const int rr = mt * 16 + gid;
        #pragma unroll
        for (int kb = 0; kb < 4; kb++) {
            float4 v0 = sx4[rr * 17 + tig * 4 + kb];
            float4 v1 = sx4[(rr + 8) * 17 + tig * 4 + kb];
            Ax[kb][0] = h2(v0.x, v0.y);  Ax[kb][2] = h2(v0.z, v0.w);
            Ax[kb][1] = h2(v1.x, v1.y);  Ax[kb][3] = h2(v1.z, v1.w);
        }
    }
    unsigned Bx[4][2];
    {
        const int rb = nt * 8 + gid;
        #pragma unroll
        for (int kb = 0; kb < 4; kb++) {
            float4 v = sx4[rb * 17 + tig * 4 + kb];
            Bx[kb][0] = h2(v.x, v.y);
            Bx[kb][1] = h2(v.z, v.w);
        }
    }

    // ---- a-loop (all 32 a's), unrolled x2; G init = bias ----
    float logit[4] = {0.0f, 0.0f, 0.0f, 0.0f};

    #pragma unroll 1
    for (int a0 = 0; a0 < AA; a0 += 2) {
        const int a1 = a0 + 1;
        const float bb0 = sb1[a0], bb1 = sb1[a1];
        float G0[4] = {bb0, bb0, bb0, bb0};
        float G1[4] = {bb1, bb1, bb1, bb1};
        uint4 u00 = sWh4[(a0 * 4 + tig) * 2];
        uint4 u01 = sWh4[(a0 * 4 + tig) * 2 + 1];
        uint4 u10 = sWh4[(a1 * 4 + tig) * 2];
        uint4 u11 = sWh4[(a1 * 4 + tig) * 2 + 1];
        const unsigned c0[4][2] = {{u00.x,u00.y},{u00.z,u00.w},{u01.x,u01.y},{u01.z,u01.w}};
        const unsigned c1[4][2] = {{u10.x,u10.y},{u10.z,u10.w},{u11.x,u11.y},{u11.z,u11.w}};
        #pragma unroll
        for (int kb = 0; kb < 4; kb++) {
            unsigned z00 = hmul2u(Bx[kb][0], c0[kb][0]);
            unsigned z01 = hmul2u(Bx[kb][1], c0[kb][1]);
            mma_f16(G0, Ax[kb][0], Ax[kb][1], Ax[kb][2], Ax[kb][3], z00, z01);
            unsigned z10 = hmul2u(Bx[kb][0], c1[kb][0]);
            unsigned z11 = hmul2u(Bx[kb][1], c1[kb][1]);
            mma_f16(G1, Ax[kb][0], Ax[kb][1], Ax[kb][2], Ax[kb][3], z10, z11);
        }
        const float ww0 = sw2[a0], ww1 = sw2[a1];
        #pragma unroll
        for (int q = 0; q < 4; q++) {
            logit[q] = fmaf(fmaxf(G0[q], 0.0f), ww0, logit[q]);
            logit[q] = fmaf(fmaxf(G1[q], 0.0f), ww1, logit[q]);
        }
    }

    // ---- p pass: s = x_i^T diag(p) x_j for this tile -> sS ----
    {
        float G[4] = {0.0f, 0.0f, 0.0f, 0.0f};
        uint4 u0 = sWh4[(AA * 4 + tig) * 2];
        uint4 u1 = sWh4[(AA * 4 + tig) * 2 + 1];
        const unsigned sc[4][2] = {{u0.x,u0.y},{u0.z,u0.w},{u1.x,u1.y},{u1.z,u1.w}};
        #pragma unroll
        for (int kb = 0; kb < 4; kb++) {
            unsigned z0 = hmul2u(Bx[kb][0], sc[kb][0]);
            unsigned z1 = hmul2u(Bx[kb][1], sc[kb][1]);
            mma_f16(G, Ax[kb][0], Ax[kb][1], Ax[kb][2], Ax[kb][3], z0, z1);
        }
        const int m0 = mt * 16 + gid, j0 = nt * 8 + 2 * tig;
        sS[m0 * NCOL + j0]           = G[0];
        sS[m0 * NCOL + j0 + 1]       = G[1];
        sS[(m0 + 8) * NCOL + j0]     = G[2];
        sS[(m0 + 8) * NCOL + j0 + 1] = G[3];
        sL[m0 * NCOL + j0]           = logit[0];
        sL[m0 * NCOL + j0 + 1]       = logit[1];
        sL[(m0 + 8) * NCOL + j0]     = logit[2];
        sL[(m0 + 8) * NCOL + j0 + 1] = logit[3];
    }
    __syncthreads();

    // ---- masked softmax over strict upper triangle (j > i) + weighted sum ----
    float lmax = -INFINITY;
    for (int t = tid; t < NF * NCOL; t += NTH) {
        int i = t / NCOL, j = t - i * NCOL;
        if (j > i) lmax = fmaxf(lmax, sL[t]);
    }
    #pragma unroll
    for (int o = 16; o > 0; o >>= 1)
        lmax = fmaxf(lmax, __shfl_xor_sync(0xFFFFFFFFu, lmax, o));
    if (lane == 0) red[wrp] = lmax;
    __syncthreads();
    if (tid == 0) {
        float m = red[0];
        #pragma unroll
        for (int w = 1; w < NW; w++) m = fmaxf(m, red[w]);
        red[32] = m;
    }
    __syncthreads();
    const float mx = red[32];

    float num = 0.0f, den = 0.0f;
    for (int t = tid; t < NF * NCOL; t += NTH) {
        int i = t / NCOL, j = t - i * NCOL;
        if (j > i) {
            float e = __expf(sL[t] - mx);
            num = fmaf(e, sS[t], num);
            den += e;
        }
    }
    #pragma unroll
    for (int o = 16; o > 0; o >>= 1) {
        num += __shfl_xor_sync(0xFFFFFFFFu, num, o);
        den += __shfl_xor_sync(0xFFFFFFFFu, den, o);
    }
    __syncthreads();
    if (lane == 0) { red[wrp] = num; red[16 + wrp] = den; }
    __syncthreads();
    if (tid == 0) {
        float n = 0.0f, d = 0.0f;
        #pragma unroll
        for (int w = 0; w < NW; w++) { n += red[w]; d += red[16 + w]; }
        out[b] = n / d;
    }
}

extern "C" void kernel_launch(void* const* d_in, const int* in_sizes, int n_in,
                              void* d_out, int out_size)
{
    const float* x    = (const float*)d_in[0];
    const float* W1   = (const float*)d_in[1];
    const float* b1   = (const float*)d_in[2];
    const float* w2   = (const float*)d_in[3];
    const float* pvec = (const float*)d_in[4];
    float* out = (float*)d_out;

    int B = in_sizes[0] / (NF * DD);
    afm_kernel<<<B, NTH>>>(x, W1, b1, w2, pvec, out);
}